// round 9
// baseline (speedup 1.0000x reference)
#include <cuda_runtime.h>

typedef unsigned long long u64;

static __device__ __forceinline__ u64 pack2(float v) {
    u64 r; asm("mov.b64 %0, {%1, %1};" : "=l"(r) : "f"(v)); return r;
}
static __device__ __forceinline__ u64 mul2(u64 a, u64 b) {
    u64 r; asm("mul.rn.f32x2 %0, %1, %2;" : "=l"(r) : "l"(a), "l"(b)); return r;
}
static __device__ __forceinline__ u64 fma2(u64 a, u64 b, u64 c) {
    u64 r; asm("fma.rn.f32x2 %0, %1, %2, %3;" : "=l"(r) : "l"(a), "l"(b), "l"(c)); return r;
}
static __device__ __forceinline__ u64 ldg64(const u64* p) {
    u64 r; asm("ld.global.nc.b64 %0, [%1];" : "=l"(r) : "l"(p)); return r;
}
static __device__ __forceinline__ void st64cs(float* p, u64 a) {
    asm volatile("st.global.cs.u64 [%0], %1;" :: "l"(p), "l"(a));
}
static __device__ __forceinline__ void st32cs(float* p, float a) {
    asm volatile("st.global.cs.f32 [%0], %1;" :: "l"(p), "f"(a));
}

// Multi-res trilinear sampling. Levels 1 (64^3x32), 2 (32^3x64), 3 (16^3x128).
// Out per point: [32 | 64 | 128 | mesh 3] = 227 floats.
// Block = 256 threads = 2 points; 128 threads/point, 2 channels/thread.
//   slot 0..15 -> lev1, 16..47 -> lev2, 48..111 -> lev3, 112 -> mesh.
// Per-(point,level) setup computed ONCE by 6 threads, broadcast via smem.
__global__ void __launch_bounds__(256) trilerp_kernel(
    const float* __restrict__ f1, const float* __restrict__ f2, const float* __restrict__ f3,
    const float* __restrict__ coords, const float* __restrict__ meshf,
    float* __restrict__ out, int Npts)
{
    // entry e = localPt*3 + (lev-1):  6 packed weights + {base, dxs, dys, dzs}
    __shared__ u64 sW[6][6];
    __shared__ int4 sI[6];

    int tid = threadIdx.x;
    int b = blockIdx.y;
    int pt0 = blockIdx.x * 2;            // first of the 2 points in this block

    // ---- phase 1: 6 threads compute per-(point,level) setup ----
    if (tid < 6) {
        int lp  = tid >> 1;              // 0,0,1,1,2,2 -> no; need pt=tid/3
        int pt  = tid / 3;               // 0 or 1
        int lev = tid - pt * 3 + 1;      // 1..3
        int pInB = pt0 + pt;
        if (pInB < Npts) {
            int point = b * Npts + pInB;
            float cx = __ldg(coords + point * 3 + 0);
            float cy = __ldg(coords + point * 3 + 1);
            float cz = __ldg(coords + point * 3 + 2);

            int R  = 128 >> lev;         // 64 / 32 / 16
            int s2 = 8 << lev;           // C/2 = 16 / 32 / 64 (float2 units)

            float scale = (float)R;
            float hi = scale - 1.01f;
            float ix = fminf(fmaxf(cx * scale, 0.01f), hi);
            float iy = fminf(fmaxf(cy * scale, 0.01f), hi);
            float iz = fminf(fmaxf(cz * scale, 0.01f), hi);

            float fx1 = floorf(ix), fx2 = ceilf(ix);
            float fy1 = floorf(iy), fy2 = ceilf(iy);
            float fz1 = floorf(iz), fz2 = ceilf(iz);

            int e = tid;
            sW[e][0] = pack2(ix - fx1);  sW[e][1] = pack2(fx2 - ix);
            sW[e][2] = pack2(iy - fy1);  sW[e][3] = pack2(fy2 - iy);
            sW[e][4] = pack2(iz - fz1);  sW[e][5] = pack2(fz2 - iz);

            int x1 = (int)fx1, y1 = (int)fy1, z1 = (int)fz1;
            int4 I;
            I.x = (((b * R + x1) * R + y1) * R + z1) * s2;   // base (float2 units)
            I.y = ((int)fx2 - x1) * R * R * s2;              // dxs
            I.z = ((int)fy2 - y1) * R * s2;                  // dys
            I.w = ((int)fz2 - z1) * s2;                      // dzs
            sI[e] = I;
        }
        (void)lp;
    }
    __syncthreads();

    // ---- phase 2: sampling ----
    int pt = tid >> 7;                   // 0 or 1
    int slot = tid & 127;
    int pInB = pt0 + pt;
    if (pInB >= Npts) return;
    int point = b * Npts + pInB;
    size_t obase = (size_t)point * 227;

    if (slot >= 112) {
        if (slot == 112) {
            st32cs(out + obase + 224, __ldg(meshf + point * 3 + 0));
            st32cs(out + obase + 225, __ldg(meshf + point * 3 + 1));
            st32cs(out + obase + 226, __ldg(meshf + point * 3 + 2));
        }
        return;
    }

    int lev = (slot < 16) ? 1 : ((slot < 48) ? 2 : 3);
    const float* __restrict__ feat = (lev == 1) ? f1 : ((lev == 2) ? f2 : f3);
    int cstart = (lev == 1) ? 0 : ((lev == 2) ? 16 : 48);
    int e = pt * 3 + lev - 1;

    u64 WX  = sW[e][0], WX2 = sW[e][1];
    u64 WY  = sW[e][2], WY2 = sW[e][3];
    u64 WZ  = sW[e][4], WZ2 = sW[e][5];
    int4 I = sI[e];
    int dxs = I.y, dys = I.z, dzs = I.w;

    const u64* p = (const u64*)feat + I.x + (slot - cstart);

    // 8 independent dense LDG.64s (warp footprint contiguous -> floor wavefronts)
    u64 v111 = ldg64(p);
    u64 v211 = ldg64(p + dxs);
    u64 v121 = ldg64(p + dys);
    u64 v221 = ldg64(p + dxs + dys);
    u64 v112 = ldg64(p + dzs);
    u64 v212 = ldg64(p + dxs + dzs);
    u64 v122 = ldg64(p + dys + dzs);
    u64 v222 = ldg64(p + dxs + dys + dzs);

    u64 la = fma2(v211, WX, mul2(v111, WX2));
    u64 lb = fma2(v221, WX, mul2(v121, WX2));
    u64 l1 = fma2(lb, WY, mul2(la, WY2));
    u64 lc = fma2(v212, WX, mul2(v112, WX2));
    u64 ld = fma2(v222, WX, mul2(v122, WX2));
    u64 l2 = fma2(ld, WY, mul2(lc, WY2));
    u64 r  = fma2(l2, WZ, mul2(l1, WZ2));

    float* q = out + obase + 2 * slot;
    if ((obase & 1) == 0) {
        st64cs(q, r);
    } else {
        float r0, r1;
        asm("mov.b64 {%0,%1}, %2;" : "=f"(r0), "=f"(r1) : "l"(r));
        st32cs(q + 0, r0);
        st32cs(q + 1, r1);
    }
}

extern "C" void kernel_launch(void* const* d_in, const int* in_sizes, int n_in,
                              void* d_out, int out_size)
{
    // metadata order: features0..features4, mesh_coords, mesh_features
    const float* f1     = (const float*)d_in[1];
    const float* f2     = (const float*)d_in[2];
    const float* f3     = (const float*)d_in[3];
    const float* coords = (const float*)d_in[5];
    const float* meshf  = (const float*)d_in[6];
    float* out = (float*)d_out;

    int B    = in_sizes[1] / (64 * 64 * 64 * 32);
    int BN   = in_sizes[5] / 3;
    int Npts = BN / B;

    dim3 grid((unsigned)((Npts + 1) / 2), (unsigned)B);
    trilerp_kernel<<<grid, 256>>>(f1, f2, f3, coords, meshf, out, Npts);
}

// round 10
// speedup vs baseline: 1.4401x; 1.4401x over previous
#include <cuda_runtime.h>

typedef unsigned long long u64;

// ---- packed f32x2 helpers (Blackwell; ptxas won't auto-fuse) ----
static __device__ __forceinline__ u64 pack2(float v) {
    u64 r; asm("mov.b64 %0, {%1, %1};" : "=l"(r) : "f"(v)); return r;
}
static __device__ __forceinline__ u64 mul2(u64 a, u64 b) {
    u64 r; asm("mul.rn.f32x2 %0, %1, %2;" : "=l"(r) : "l"(a), "l"(b)); return r;
}
static __device__ __forceinline__ u64 fma2(u64 a, u64 b, u64 c) {
    u64 r; asm("fma.rn.f32x2 %0, %1, %2, %3;" : "=l"(r) : "l"(a), "l"(b), "l"(c)); return r;
}
struct P4 { u64 a, b; };

// One 128-bit non-coherent load per corner: minimum L1 wavefronts
// (lane-contiguous rows -> wavefronts == lines touched).
static __device__ __forceinline__ P4 ld4v(const float4* __restrict__ p) {
    P4 r;
    asm("ld.global.nc.v2.u64 {%0, %1}, [%2];" : "=l"(r.a), "=l"(r.b) : "l"(p));
    return r;
}
static __device__ __forceinline__ P4 lerp4p(P4 A, P4 B, u64 WA, u64 WB) {
    P4 r;
    r.a = fma2(A.a, WA, mul2(B.a, WB));
    r.b = fma2(A.b, WA, mul2(B.b, WB));
    return r;
}

// streaming stores: keep the 91MB output from evicting the ~78MB feature set in L2
static __device__ __forceinline__ void st128cs(float* p, u64 a, u64 b) {
    asm volatile("st.global.cs.v2.u64 [%0], {%1, %2};" :: "l"(p), "l"(a), "l"(b));
}
static __device__ __forceinline__ void st64cs(float* p, u64 a) {
    asm volatile("st.global.cs.u64 [%0], %1;" :: "l"(p), "l"(a));
}
static __device__ __forceinline__ void st32cs(float* p, float a) {
    asm volatile("st.global.cs.f32 [%0], %1;" :: "l"(p), "f"(a));
}

// Multi-res trilinear sampling. Levels 1 (64^3x32), 2 (32^3x64), 3 (16^3x128).
// Out per point: [32 | 64 | 128 | mesh 3] = 227 floats.
// 64 threads/point, 4 channels/thread:
//   slot 0..7 -> lev1, 8..23 -> lev2, 24..55 -> lev3, 56..58 -> mesh.
// Global out channel = 4*slot for slots 0..55 (concat offsets align).
// __launch_bounds__(256, 8) forces <=32 regs -> 8 blocks (64 warps)/SM resident.
__global__ void __launch_bounds__(256, 8) trilerp_kernel(
    const float* __restrict__ f1, const float* __restrict__ f2, const float* __restrict__ f3,
    const float* __restrict__ coords, const float* __restrict__ meshf,
    float* __restrict__ out, int Npts)
{
    int t = blockIdx.x * 256 + threadIdx.x;
    int pInB = t >> 6;
    if (pInB >= Npts) return;
    int slot = t & 63;
    int b = blockIdx.y;
    int point = b * Npts + pInB;
    size_t obase = (size_t)point * 227;

    if (slot >= 56) {
        int k = slot - 56;
        if (k < 3) st32cs(out + obase + 224 + k, __ldg(meshf + point * 3 + k));
        return;
    }

    float cx = __ldg(coords + point * 3 + 0);
    float cy = __ldg(coords + point * 3 + 1);
    float cz = __ldg(coords + point * 3 + 2);

    int lev = (slot < 8) ? 1 : ((slot < 24) ? 2 : 3);
    const float4* __restrict__ fp =
        (const float4*)((lev == 1) ? f1 : ((lev == 2) ? f2 : f3));
    int cstart = (lev == 1) ? 0 : ((lev == 2) ? 8 : 24);
    int R  = 128 >> lev;         // 64 / 32 / 16
    int s4 = 4 << lev;           // C/4 = 8 / 16 / 32
    int c4 = slot - cstart;      // channel base in float4 units

    float scale = (float)R;      // 0.5^lev * 128 == R
    float hi = scale - 1.01f;
    float ix = fminf(fmaxf(cx * scale, 0.01f), hi);
    float iy = fminf(fmaxf(cy * scale, 0.01f), hi);
    float iz = fminf(fmaxf(cz * scale, 0.01f), hi);

    float fx1 = floorf(ix), fx2 = ceilf(ix);
    float fy1 = floorf(iy), fy2 = ceilf(iy);
    float fz1 = floorf(iz), fz2 = ceilf(iz);

    u64 WX = pack2(ix - fx1), WX2 = pack2(fx2 - ix);
    u64 WY = pack2(iy - fy1), WY2 = pack2(fy2 - iy);
    u64 WZ = pack2(iz - fz1), WZ2 = pack2(fz2 - iz);

    int x1 = (int)fx1, y1 = (int)fy1, z1 = (int)fz1;
    // corner step offsets (0 or one full stride) in float4 units
    int dxs = ((int)fx2 - x1) * R * R * s4;
    int dys = ((int)fy2 - y1) * R * s4;
    int dzs = ((int)fz2 - z1) * s4;
    const float4* p = fp + (((b * R + x1) * R + y1) * R + z1) * s4 + c4;

    // 8 independent LDG.128s (front-batched; wavefronts = lines = floor)
    P4 v111 = ld4v(p);
    P4 v211 = ld4v(p + dxs);
    P4 v121 = ld4v(p + dys);
    P4 v221 = ld4v(p + dxs + dys);
    P4 v112 = ld4v(p + dzs);
    P4 v212 = ld4v(p + dxs + dzs);
    P4 v122 = ld4v(p + dys + dzs);
    P4 v222 = ld4v(p + dxs + dys + dzs);

    // z = z1 plane
    P4 la = lerp4p(v211, v111, WX, WX2);
    P4 lb = lerp4p(v221, v121, WX, WX2);
    P4 l1 = lerp4p(lb, la, WY, WY2);
    // z = z2 plane
    P4 lc = lerp4p(v212, v112, WX, WX2);
    P4 ld_ = lerp4p(v222, v122, WX, WX2);
    P4 l2 = lerp4p(ld_, lc, WY, WY2);

    P4 r = lerp4p(l2, l1, WZ, WZ2);

    // out alignment class is warp-uniform (4*slot ≡ 0 mod 4; obase mod 4 fixed per point)
    unsigned omod = (unsigned)(obase & 3);
    float* q = out + obase + 4 * slot;
    if (omod == 0) {
        st128cs(q, r.a, r.b);                 // STG.128
    } else if ((omod & 1) == 0) {
        st64cs(q, r.a);                       // 2x STG.64
        st64cs(q + 2, r.b);
    } else {
        float a0, a1, b0, b1;
        asm("mov.b64 {%0,%1}, %2;" : "=f"(a0), "=f"(a1) : "l"(r.a));
        asm("mov.b64 {%0,%1}, %2;" : "=f"(b0), "=f"(b1) : "l"(r.b));
        st32cs(q + 0, a0); st32cs(q + 1, a1);
        st32cs(q + 2, b0); st32cs(q + 3, b1);
    }
}

extern "C" void kernel_launch(void* const* d_in, const int* in_sizes, int n_in,
                              void* d_out, int out_size)
{
    // metadata order: features0..features4, mesh_coords, mesh_features
    const float* f1     = (const float*)d_in[1];
    const float* f2     = (const float*)d_in[2];
    const float* f3     = (const float*)d_in[3];
    const float* coords = (const float*)d_in[5];
    const float* meshf  = (const float*)d_in[6];
    float* out = (float*)d_out;

    int B    = in_sizes[1] / (64 * 64 * 64 * 32);
    int BN   = in_sizes[5] / 3;
    int Npts = BN / B;

    long long tpb = (long long)Npts * 64;
    dim3 grid((unsigned)((tpb + 255) / 256), (unsigned)B);
    trilerp_kernel<<<grid, 256>>>(f1, f2, f3, coords, meshf, out, Npts);
}